// round 11
// baseline (speedup 1.0000x reference)
#include <cuda_runtime.h>
#include <cuda_fp16.h>
#include <cuda_bf16.h>

#define NNODES 50000
#define NEDGES 800000
#define FIN    128
#define BN_EPS 1e-5f
#define NCHUNK ((NNODES + 1023) / 1024)   // 49

// ---------------- scratch (device globals: no allocs allowed) ----------------
__device__ __half g_bufH[NNODES * 128];   // GEMM out (hs, fp16) -> agg gathers
__device__ __half g_bufG[NNODES * 128];   // agg out (fp16) -> next GEMM A
__device__ int    g_deg[NNODES];          // zero at entry (re-zeroed by scanB)
__device__ int    g_rowptr[NNODES + 1];
__device__ unsigned short g_rank16[NEDGES];
__device__ int    g_col[NEDGES];
__device__ float  g_dinv[NNODES];
__device__ int    g_bsum[NCHUNK];

// ---------------- CSR build ----------------
__global__ void hist_rank_k(const int* __restrict__ ei) {
    int e4 = blockIdx.x * blockDim.x + threadIdx.x;
    if (e4 < NEDGES / 4) {
        int4 d = ((const int4*)(ei + NEDGES))[e4];
        ushort4 r;
        r.x = (unsigned short)atomicAdd(&g_deg[d.x], 1);
        r.y = (unsigned short)atomicAdd(&g_deg[d.y], 1);
        r.z = (unsigned short)atomicAdd(&g_deg[d.z], 1);
        r.w = (unsigned short)atomicAdd(&g_deg[d.w], 1);
        ((ushort4*)g_rank16)[e4] = r;
    }
}

__global__ void scan1_k() {
    __shared__ int ws[8];
    int b = blockIdx.x, tid = threadIdx.x, lane = tid & 31, wid = tid >> 5;
    int base = b * 1024 + tid * 4;
    int s = 0;
    #pragma unroll
    for (int u = 0; u < 4; u++) {
        int i = base + u;
        if (i < NNODES) s += g_deg[i];
    }
    #pragma unroll
    for (int off = 16; off > 0; off >>= 1)
        s += __shfl_down_sync(0xffffffff, s, off);
    if (lane == 0) ws[wid] = s;
    __syncthreads();
    if (tid == 0) {
        int t = 0;
        #pragma unroll
        for (int w = 0; w < 8; w++) t += ws[w];
        g_bsum[b] = t;
    }
}

// per-chunk scan; each block derives its own carry; zeroes g_deg
__global__ void scanB_k() {
    __shared__ int wsum[32];
    __shared__ int carry;
    int b = blockIdx.x, tid = threadIdx.x, lane = tid & 31, wid = tid >> 5;

    if (wid == 0) {
        int v0 = (lane < b) ? g_bsum[lane] : 0;
        int v1 = (lane + 32 < b) ? g_bsum[lane + 32] : 0;
        int s = v0 + v1;
        #pragma unroll
        for (int off = 16; off > 0; off >>= 1)
            s += __shfl_down_sync(0xffffffff, s, off);
        if (lane == 0) carry = s;
    }

    int i = b * 1024 + tid;
    int v = (i < NNODES) ? g_deg[i] : 0;
    int incl = v;
    #pragma unroll
    for (int off = 1; off < 32; off <<= 1) {
        int t = __shfl_up_sync(0xffffffff, incl, off);
        if (lane >= off) incl += t;
    }
    if (lane == 31) wsum[wid] = incl;
    __syncthreads();
    if (wid == 0) {
        int s = wsum[lane];
        #pragma unroll
        for (int off = 1; off < 32; off <<= 1) {
            int t = __shfl_up_sync(0xffffffff, s, off);
            if (lane >= off) s += t;
        }
        wsum[lane] = s;
    }
    __syncthreads();
    if (i < NNODES) {
        int o = carry + (wid ? wsum[wid - 1] : 0) + incl - v;  // exclusive
        g_rowptr[i] = o;
        g_dinv[i]   = rsqrtf(1.0f + (float)v);
        g_deg[i]    = 0;
    }
    if (b == 0 && tid == 0) g_rowptr[NNODES] = NEDGES;
}

__global__ void scatter_k(const int* __restrict__ ei) {
    int e4 = blockIdx.x * blockDim.x + threadIdx.x;
    if (e4 < NEDGES / 4) {
        int4 s = ((const int4*)ei)[e4];
        int4 d = ((const int4*)(ei + NEDGES))[e4];
        ushort4 r = ((const ushort4*)g_rank16)[e4];
        g_col[g_rowptr[d.x] + r.x] = s.x;
        g_col[g_rowptr[d.y] + r.y] = s.y;
        g_col[g_rowptr[d.z] + r.z] = s.z;
        g_col[g_rowptr[d.w] + r.w] = s.w;
    }
}

// ---------------- bf16 / fp16 helpers ----------------
__device__ __forceinline__ void split2b(float v0, float v1, unsigned& hi, unsigned& lo) {
    __nv_bfloat16 h0 = __float2bfloat16_rn(v0);
    __nv_bfloat16 h1 = __float2bfloat16_rn(v1);
    float l0 = v0 - __bfloat162float(h0);
    float l1 = v1 - __bfloat162float(h1);
    __nv_bfloat162 hp; hp.x = h0; hp.y = h1;
    hi = *(unsigned*)&hp;
    __nv_bfloat162 lp = __floats2bfloat162_rn(l0, l1);
    lo = *(unsigned*)&lp;
}

__device__ __forceinline__ void mma_bf16(
    float& c0, float& c1, float& c2, float& c3,
    unsigned a0, unsigned a1, unsigned a2, unsigned a3,
    unsigned b0, unsigned b1)
{
    asm volatile(
        "mma.sync.aligned.m16n8k16.row.col.f32.bf16.bf16.f32 "
        "{%0,%1,%2,%3}, {%4,%5,%6,%7}, {%8,%9}, {%0,%1,%2,%3};"
        : "+f"(c0), "+f"(c1), "+f"(c2), "+f"(c3)
        : "r"(a0), "r"(a1), "r"(a2), "r"(a3), "r"(b0), "r"(b1));
}

__device__ __forceinline__ void split2h(float v0, float v1, unsigned& hi, unsigned& lo) {
    __half h0 = __float2half_rn(v0);
    __half h1 = __float2half_rn(v1);
    float l0 = v0 - __half2float(h0);
    float l1 = v1 - __half2float(h1);
    __half2 hp; hp.x = h0; hp.y = h1;
    hi = *(unsigned*)&hp;
    __half2 lp = __floats2half2_rn(l0, l1);
    lo = *(unsigned*)&lp;
}

__device__ __forceinline__ void mma_f16(
    float& c0, float& c1, float& c2, float& c3,
    unsigned a0, unsigned a1, unsigned a2, unsigned a3,
    unsigned b0, unsigned b1)
{
    asm volatile(
        "mma.sync.aligned.m16n8k16.row.col.f32.f16.f16.f32 "
        "{%0,%1,%2,%3}, {%4,%5,%6,%7}, {%8,%9}, {%0,%1,%2,%3};"
        : "+f"(c0), "+f"(c1), "+f"(c2), "+f"(c3)
        : "r"(a0), "r"(a1), "r"(a2), "r"(a3), "r"(b0), "r"(b1));
}

// ------------- layer-1 GEMM: g_bufH = (x @ W1), bf16 3-term, fp16 out --------
__global__ __launch_bounds__(256) void gemm1_k(
    const float* __restrict__ A, const float* __restrict__ W)
{
    const int FOUT = 128, MW = 4, NW = 2;
    const int BM = 128, BK = 16, K2 = BK / 2;
    const int MT = BM / (16 * MW);
    const int NT = FOUT / (8 * NW);
    const int APAD = BM + 8;
    const int WPAD = FOUT + 8;

    __shared__ unsigned Ap_hi[K2][APAD], Ap_lo[K2][APAD];
    __shared__ unsigned Wp_hi[K2][WPAD], Wp_lo[K2][WPAD];

    int tid  = threadIdx.x;
    int lane = tid & 31;
    int wid  = tid >> 5;
    int warp_m = wid % MW;
    int warp_n = wid / MW;
    int rb = blockIdx.x * BM;

    float c[MT][NT][4];
    #pragma unroll
    for (int mt = 0; mt < MT; mt++)
        #pragma unroll
        for (int nt = 0; nt < NT; nt++)
            #pragma unroll
            for (int q = 0; q < 4; q++) c[mt][nt][q] = 0.0f;

    for (int kt = 0; kt < FIN; kt += BK) {
        #pragma unroll
        for (int t = 0; t < 2; t++) {
            int idx = tid + t * 256;
            int r = idx >> 2, q = idx & 3;
            int row = rb + r;
            float4 v = make_float4(0.f, 0.f, 0.f, 0.f);
            if (row < NNODES)
                v = *(const float4*)&A[(size_t)row * FIN + kt + q * 4];
            unsigned h, l;
            split2b(v.x, v.y, h, l); Ap_hi[q * 2][r] = h;     Ap_lo[q * 2][r] = l;
            split2b(v.z, v.w, h, l); Ap_hi[q * 2 + 1][r] = h; Ap_lo[q * 2 + 1][r] = l;
        }
        {
            int k2 = tid >> 5, q = tid & 31;
            float4 v0 = *(const float4*)&W[(size_t)(kt + 2 * k2) * FOUT + q * 4];
            float4 v1 = *(const float4*)&W[(size_t)(kt + 2 * k2 + 1) * FOUT + q * 4];
            unsigned h, l;
            split2b(v0.x, v1.x, h, l); Wp_hi[k2][q * 4 + 0] = h; Wp_lo[k2][q * 4 + 0] = l;
            split2b(v0.y, v1.y, h, l); Wp_hi[k2][q * 4 + 1] = h; Wp_lo[k2][q * 4 + 1] = l;
            split2b(v0.z, v1.z, h, l); Wp_hi[k2][q * 4 + 2] = h; Wp_lo[k2][q * 4 + 2] = l;
            split2b(v0.w, v1.w, h, l); Wp_hi[k2][q * 4 + 3] = h; Wp_lo[k2][q * 4 + 3] = l;
        }
        __syncthreads();

        int t4 = lane & 3;
        int g  = lane >> 2;
        unsigned ahi[MT][4], alo[MT][4];
        #pragma unroll
        for (int mt = 0; mt < MT; mt++) {
            int m = warp_m * (MT * 16) + mt * 16 + g;
            ahi[mt][0] = Ap_hi[t4][m];         alo[mt][0] = Ap_lo[t4][m];
            ahi[mt][1] = Ap_hi[t4][m + 8];     alo[mt][1] = Ap_lo[t4][m + 8];
            ahi[mt][2] = Ap_hi[t4 + 4][m];     alo[mt][2] = Ap_lo[t4 + 4][m];
            ahi[mt][3] = Ap_hi[t4 + 4][m + 8]; alo[mt][3] = Ap_lo[t4 + 4][m + 8];
        }
        #pragma unroll
        for (int nt = 0; nt < NT; nt++) {
            int n = warp_n * (NT * 8) + nt * 8 + g;
            unsigned bh0 = Wp_hi[t4][n], bh1 = Wp_hi[t4 + 4][n];
            unsigned bl0 = Wp_lo[t4][n], bl1 = Wp_lo[t4 + 4][n];
            #pragma unroll
            for (int mt = 0; mt < MT; mt++) {
                mma_bf16(c[mt][nt][0], c[mt][nt][1], c[mt][nt][2], c[mt][nt][3],
                         ahi[mt][0], ahi[mt][1], ahi[mt][2], ahi[mt][3], bh0, bh1);
                mma_bf16(c[mt][nt][0], c[mt][nt][1], c[mt][nt][2], c[mt][nt][3],
                         ahi[mt][0], ahi[mt][1], ahi[mt][2], ahi[mt][3], bl0, bl1);
                mma_bf16(c[mt][nt][0], c[mt][nt][1], c[mt][nt][2], c[mt][nt][3],
                         alo[mt][0], alo[mt][1], alo[mt][2], alo[mt][3], bh0, bh1);
            }
        }
        __syncthreads();
    }

    #pragma unroll
    for (int mt = 0; mt < MT; mt++) {
        int r0 = rb + warp_m * (MT * 16) + mt * 16 + (lane >> 2);
        int colb = warp_n * (NT * 8) + (lane & 3) * 2;
        #pragma unroll
        for (int half = 0; half < 2; half++) {
            int row = half ? (r0 + 8) : r0;
            int q0 = half * 2;
            if (row < NNODES) {
                #pragma unroll
                for (int nt = 0; nt < NT; nt++)
                    *(__half2*)&g_bufH[(size_t)row * FOUT + colb + nt * 8] =
                        __floats2half2_rn(c[mt][nt][q0], c[mt][nt][q0 + 1]);
            }
        }
    }
}

// ------- layer-2/3 GEMM: g_bufH = (g_bufG @ W) * dinv, fp16 A, 2-term W ------
template <int FOUT, int MW, int NW>
__global__ __launch_bounds__(256) void gemm_h_k(const float* __restrict__ W)
{
    const int BM = 128, BK = 16, K2 = BK / 2;
    const int MT = BM / (16 * MW);
    const int NT = FOUT / (8 * NW);
    const int APAD = BM + 8;
    const int WPAD = FOUT + 8;

    __shared__ unsigned Ap[K2][APAD];
    __shared__ unsigned Wp_hi[K2][WPAD], Wp_lo[K2][WPAD];

    int tid  = threadIdx.x;
    int lane = tid & 31;
    int wid  = tid >> 5;
    int warp_m = wid % MW;
    int warp_n = wid / MW;
    int rb = blockIdx.x * BM;

    float c[MT][NT][4];
    #pragma unroll
    for (int mt = 0; mt < MT; mt++)
        #pragma unroll
        for (int nt = 0; nt < NT; nt++)
            #pragma unroll
            for (int q = 0; q < 4; q++) c[mt][nt][q] = 0.0f;

    for (int kt = 0; kt < FIN; kt += BK) {
        {
            int r = tid & 127, q = tid >> 7;
            int row = rb + r;
            uint4 v = make_uint4(0, 0, 0, 0);
            if (row < NNODES)
                v = *(const uint4*)&g_bufG[(size_t)row * FIN + kt + q * 8];
            Ap[q * 4 + 0][r] = v.x;
            Ap[q * 4 + 1][r] = v.y;
            Ap[q * 4 + 2][r] = v.z;
            Ap[q * 4 + 3][r] = v.w;
        }
        {
            int tasks = K2 * (FOUT / 4);
            if (tid < tasks) {
                int k2 = tid / (FOUT / 4), q = tid % (FOUT / 4);
                float4 v0 = *(const float4*)&W[(size_t)(kt + 2 * k2) * FOUT + q * 4];
                float4 v1 = *(const float4*)&W[(size_t)(kt + 2 * k2 + 1) * FOUT + q * 4];
                unsigned h, l;
                split2h(v0.x, v1.x, h, l); Wp_hi[k2][q * 4 + 0] = h; Wp_lo[k2][q * 4 + 0] = l;
                split2h(v0.y, v1.y, h, l); Wp_hi[k2][q * 4 + 1] = h; Wp_lo[k2][q * 4 + 1] = l;
                split2h(v0.z, v1.z, h, l); Wp_hi[k2][q * 4 + 2] = h; Wp_lo[k2][q * 4 + 2] = l;
                split2h(v0.w, v1.w, h, l); Wp_hi[k2][q * 4 + 3] = h; Wp_lo[k2][q * 4 + 3] = l;
            }
        }
        __syncthreads();

        int t4 = lane & 3;
        int g  = lane >> 2;
        unsigned a[MT][4];
        #pragma unroll
        for (int mt = 0; mt < MT; mt++) {
            int m = warp_m * (MT * 16) + mt * 16 + g;
            a[mt][0] = Ap[t4][m];
            a[mt][1] = Ap[t4][m + 8];
            a[mt][2] = Ap[t4 + 4][m];
            a[mt][3] = Ap[t4 + 4][m + 8];
        }
        #pragma unroll
        for (int nt = 0; nt < NT; nt++) {
            int n = warp_n * (NT * 8) + nt * 8 + g;
            unsigned bh0 = Wp_hi[t4][n], bh1 = Wp_hi[t4 + 4][n];
            unsigned bl0 = Wp_lo[t4][n], bl1 = Wp_lo[t4 + 4][n];
            #pragma unroll
            for (int mt = 0; mt < MT; mt++) {
                mma_f16(c[mt][nt][0], c[mt][nt][1], c[mt][nt][2], c[mt][nt][3],
                        a[mt][0], a[mt][1], a[mt][2], a[mt][3], bh0, bh1);
                mma_f16(c[mt][nt][0], c[mt][nt][1], c[mt][nt][2], c[mt][nt][3],
                        a[mt][0], a[mt][1], a[mt][2], a[mt][3], bl0, bl1);
            }
        }
        __syncthreads();
    }

    #pragma unroll
    for (int mt = 0; mt < MT; mt++) {
        int r0 = rb + warp_m * (MT * 16) + mt * 16 + (lane >> 2);
        int colb = warp_n * (NT * 8) + (lane & 3) * 2;
        #pragma unroll
        for (int half = 0; half < 2; half++) {
            int row = half ? (r0 + 8) : r0;
            int q0 = half * 2;
            if (row < NNODES) {
                float d = g_dinv[row];
                #pragma unroll
                for (int nt = 0; nt < NT; nt++)
                    *(__half2*)&g_bufH[(size_t)row * FOUT + colb + nt * 8] =
                        __floats2half2_rn(c[mt][nt][q0] * d, c[mt][nt][q0 + 1] * d);
            }
        }
    }
}

// ---------------- aggregate fp16 hs (half-warp per dst, uint4/lane, F=128) ----
// Masked full-unroll: all edge loads at MLP=8; OOB lanes clamp to g_col[beg]
// (L1-resident) and contribute 0 via the mask multiplier.
template <bool SRCSCALE>
__global__ __launch_bounds__(256) void agg128h_k(
    const float* __restrict__ bias,
    const float* __restrict__ gam, const float* __restrict__ bet,
    const float* __restrict__ mu,  const float* __restrict__ var)
{
    int dst  = blockIdx.x * 16 + (threadIdx.x >> 4);
    int lane = threadIdx.x & 15;
    if (dst >= NNODES) return;

    const uint4* hs = (const uint4*)g_bufH;   // row = 16 uint4 (8 fp16 each)

    int beg = g_rowptr[dst];
    int end = g_rowptr[dst + 1];
    float d = g_dinv[dst];

    float acc[8];
    {
        uint4 v = hs[(size_t)dst * 16 + lane];
        float2 f0 = __half22float2(*(__half2*)&v.x);
        float2 f1 = __half22float2(*(__half2*)&v.y);
        float2 f2 = __half22float2(*(__half2*)&v.z);
        float2 f3 = __half22float2(*(__half2*)&v.w);
        float sd = SRCSCALE ? d : 1.0f;
        acc[0] = f0.x * sd; acc[1] = f0.y * sd;
        acc[2] = f1.x * sd; acc[3] = f1.y * sd;
        acc[4] = f2.x * sd; acc[5] = f2.y * sd;
        acc[6] = f3.x * sd; acc[7] = f3.y * sd;
    }

    int nit = (end - beg + 7) >> 3;
    for (int it = 0; it < nit; it++) {
        int base = beg + it * 8;
        uint4 v[8]; float sc[8];
        #pragma unroll
        for (int u = 0; u < 8; u++) {
            int idx = base + u;
            bool ok = idx < end;
            int c = g_col[ok ? idx : beg];
            v[u] = hs[(size_t)c * 16 + lane];
            float s = SRCSCALE ? g_dinv[c] : 1.0f;
            sc[u] = ok ? s : 0.0f;
        }
        #pragma unroll
        for (int u = 0; u < 8; u++) {
            float2 f0 = __half22float2(*(__half2*)&v[u].x);
            float2 f1 = __half22float2(*(__half2*)&v[u].y);
            float2 f2 = __half22float2(*(__half2*)&v[u].z);
            float2 f3 = __half22float2(*(__half2*)&v[u].w);
            acc[0] = fmaf(f0.x, sc[u], acc[0]); acc[1] = fmaf(f0.y, sc[u], acc[1]);
            acc[2] = fmaf(f1.x, sc[u], acc[2]); acc[3] = fmaf(f1.y, sc[u], acc[3]);
            acc[4] = fmaf(f2.x, sc[u], acc[4]); acc[5] = fmaf(f2.y, sc[u], acc[5]);
            acc[6] = fmaf(f3.x, sc[u], acc[6]); acc[7] = fmaf(f3.y, sc[u], acc[7]);
        }
    }

    float4 b0 = ((const float4*)bias)[lane * 2], b1 = ((const float4*)bias)[lane * 2 + 1];
    float4 g0 = ((const float4*)gam)[lane * 2],  g1 = ((const float4*)gam)[lane * 2 + 1];
    float4 t0 = ((const float4*)bet)[lane * 2],  t1 = ((const float4*)bet)[lane * 2 + 1];
    float4 m0 = ((const float4*)mu)[lane * 2],   m1 = ((const float4*)mu)[lane * 2 + 1];
    float4 v0 = ((const float4*)var)[lane * 2],  v1 = ((const float4*)var)[lane * 2 + 1];
    float bb[8] = {b0.x, b0.y, b0.z, b0.w, b1.x, b1.y, b1.z, b1.w};
    float gg[8] = {g0.x, g0.y, g0.z, g0.w, g1.x, g1.y, g1.z, g1.w};
    float tt[8] = {t0.x, t0.y, t0.z, t0.w, t1.x, t1.y, t1.z, t1.w};
    float mm[8] = {m0.x, m0.y, m0.z, m0.w, m1.x, m1.y, m1.z, m1.w};
    float vv[8] = {v0.x, v0.y, v0.z, v0.w, v1.x, v1.y, v1.z, v1.w};

    float r[8];
    #pragma unroll
    for (int q = 0; q < 8; q++) {
        float val = acc[q] * d + bb[q];
        val = (val - mm[q]) * rsqrtf(vv[q] + BN_EPS) * gg[q] + tt[q];
        r[q] = val > 0.f ? val : 0.1f * val;
    }
    uint4 o;
    *(__half2*)&o.x = __floats2half2_rn(r[0], r[1]);
    *(__half2*)&o.y = __floats2half2_rn(r[2], r[3]);
    *(__half2*)&o.z = __floats2half2_rn(r[4], r[5]);
    *(__half2*)&o.w = __floats2half2_rn(r[6], r[7]);
    ((uint4*)g_bufG)[(size_t)dst * 16 + lane] = o;
}

// ---------------- aggregate F=64 fp16 hs (half-warp per dst, uint2/lane) ------
__global__ __launch_bounds__(256) void agg64h_k(
    float* __restrict__ Oext, const float* __restrict__ bias)
{
    int dst  = blockIdx.x * 16 + (threadIdx.x >> 4);
    int lane = threadIdx.x & 15;
    if (dst >= NNODES) return;

    const uint2* hs = (const uint2*)g_bufH;   // row = 16 uint2 (4 fp16 each)

    int beg = g_rowptr[dst];
    int end = g_rowptr[dst + 1];

    float acc[4];
    {
        uint2 v = hs[(size_t)dst * 16 + lane];
        float2 f0 = __half22float2(*(__half2*)&v.x);
        float2 f1 = __half22float2(*(__half2*)&v.y);
        acc[0] = f0.x; acc[1] = f0.y; acc[2] = f1.x; acc[3] = f1.y;
    }

    int nit = (end - beg + 7) >> 3;
    for (int it = 0; it < nit; it++) {
        int base = beg + it * 8;
        uint2 v[8]; float sc[8];
        #pragma unroll
        for (int u = 0; u < 8; u++) {
            int idx = base + u;
            bool ok = idx < end;
            int c = g_col[ok ? idx : beg];
            v[u] = hs[(size_t)c * 16 + lane];
            sc[u] = ok ? 1.0f : 0.0f;
        }
        #pragma unroll
        for (int u = 0; u < 8; u++) {
            float2 f0 = __half22float2(*(__half2*)&v[u].x);
            float2 f1 = __half22float2(*(__half2*)&v[u].y);
            acc[0] = fmaf(f0.x, sc[u], acc[0]); acc[1] = fmaf(f0.y, sc[u], acc[1]);
            acc[2] = fmaf(f1.x, sc[u], acc[2]); acc[3] = fmaf(f1.y, sc[u], acc[3]);
        }
    }

    float d = g_dinv[dst];
    float4 b4 = ((const float4*)bias)[lane];
    float4 r;
    r.x = acc[0] * d + b4.x;
    r.y = acc[1] * d + b4.y;
    r.z = acc[2] * d + b4.z;
    r.w = acc[3] * d + b4.w;
    ((float4*)Oext)[(size_t)dst * 16 + lane] = r;
}

// ---------------- launch ----------------
extern "C" void kernel_launch(void* const* d_in, const int* in_sizes, int n_in,
                              void* d_out, int out_size)
{
    const float* x   = (const float*)d_in[0];
    const int*   ei  = (const int*)d_in[1];
    const float* W1 = (const float*)d_in[2];
    const float* b1 = (const float*)d_in[3];
    const float* g1 = (const float*)d_in[4];
    const float* be1= (const float*)d_in[5];
    const float* m1 = (const float*)d_in[6];
    const float* v1 = (const float*)d_in[7];
    const float* W2 = (const float*)d_in[8];
    const float* b2 = (const float*)d_in[9];
    const float* g2 = (const float*)d_in[10];
    const float* be2= (const float*)d_in[11];
    const float* m2 = (const float*)d_in[12];
    const float* v2 = (const float*)d_in[13];
    const float* W3 = (const float*)d_in[14];
    const float* b3 = (const float*)d_in[15];
    float* out = (float*)d_out;

    // side stream + events, created once on the (non-captured) correctness call
    static cudaStream_t s2 = nullptr;
    static cudaEvent_t evF = nullptr, evJ = nullptr;
    if (s2 == nullptr) {
        cudaStreamCreateWithFlags(&s2, cudaStreamNonBlocking);
        cudaEventCreateWithFlags(&evF, cudaEventDisableTiming);
        cudaEventCreateWithFlags(&evJ, cudaEventDisableTiming);
    }

    const int gblk = (NNODES + 127) / 128;
    const int ablk = (NNODES + 15) / 16;

    // fork: CSR build on s2, concurrent with GEMM1 (g_deg is 0 at entry)
    cudaEventRecord(evF, 0);
    cudaStreamWaitEvent(s2, evF, 0);
    hist_rank_k<<<(NEDGES / 4 + 255) / 256, 256, 0, s2>>>(ei);
    scan1_k<<<NCHUNK, 256, 0, s2>>>();
    scanB_k<<<NCHUNK, 1024, 0, s2>>>();
    scatter_k<<<(NEDGES / 4 + 255) / 256, 256, 0, s2>>>(ei);

    // layer 1 GEMM: x @ W1 -> g_bufH fp16 (unscaled)
    gemm1_k<<<gblk, 256>>>(x, W1);

    // join
    cudaEventRecord(evJ, s2);
    cudaStreamWaitEvent(0, evJ, 0);

    // layer 1 agg (applies dinv[src] inline), BN1 + leaky -> g_bufG fp16
    agg128h_k<true><<<ablk, 256>>>(b1, g1, be1, m1, v1);

    // layer 2: fp16 GEMM (g_bufG @ W2)*dinv -> g_bufH ; agg -> g_bufG
    gemm_h_k<128, 4, 2><<<gblk, 256>>>(W2);
    agg128h_k<false><<<ablk, 256>>>(b2, g2, be2, m2, v2);

    // layer 3: fp16 GEMM (g_bufG @ W3)*dinv -> g_bufH ; agg -> out fp32
    gemm_h_k<64, 8, 1><<<gblk, 256>>>(W3);
    agg64h_k<<<ablk, 256>>>(out, b3);
}

// round 12
// speedup vs baseline: 1.0618x; 1.0618x over previous
#include <cuda_runtime.h>
#include <cuda_fp16.h>
#include <cuda_bf16.h>

#define NNODES 50000
#define NEDGES 800000
#define FIN    128
#define BN_EPS 1e-5f
#define NCHUNK ((NNODES + 1023) / 1024)   // 49

// ---------------- scratch (device globals: no allocs allowed) ----------------
__device__ __half g_bufH[NNODES * 128];   // GEMM out (hs, fp16) -> agg gathers
__device__ __half g_bufG[NNODES * 128];   // agg out (fp16) -> next GEMM A
__device__ int    g_deg[NNODES];          // zero at entry (re-zeroed by scanB)
__device__ int    g_rowptr[NNODES + 1];
__device__ unsigned short g_rank16[NEDGES];
__device__ int    g_col[NEDGES];
__device__ float  g_dinv[NNODES];
__device__ int    g_bsum[NCHUNK];

// ---------------- CSR build ----------------
// 8 edges per thread (two int4 batches) for higher MLP under atomics
__global__ void hist_rank_k(const int* __restrict__ ei) {
    int t = blockIdx.x * blockDim.x + threadIdx.x;
    int e8 = t * 2;
    if (e8 + 1 < NEDGES / 4) {
        int4 d0 = ((const int4*)(ei + NEDGES))[e8];
        int4 d1 = ((const int4*)(ei + NEDGES))[e8 + 1];
        ushort4 r0, r1;
        r0.x = (unsigned short)atomicAdd(&g_deg[d0.x], 1);
        r0.y = (unsigned short)atomicAdd(&g_deg[d0.y], 1);
        r0.z = (unsigned short)atomicAdd(&g_deg[d0.z], 1);
        r0.w = (unsigned short)atomicAdd(&g_deg[d0.w], 1);
        r1.x = (unsigned short)atomicAdd(&g_deg[d1.x], 1);
        r1.y = (unsigned short)atomicAdd(&g_deg[d1.y], 1);
        r1.z = (unsigned short)atomicAdd(&g_deg[d1.z], 1);
        r1.w = (unsigned short)atomicAdd(&g_deg[d1.w], 1);
        ((ushort4*)g_rank16)[e8] = r0;
        ((ushort4*)g_rank16)[e8 + 1] = r1;
    }
}

__global__ void scan1_k() {
    __shared__ int ws[8];
    int b = blockIdx.x, tid = threadIdx.x, lane = tid & 31, wid = tid >> 5;
    int base = b * 1024 + tid * 4;
    int s = 0;
    #pragma unroll
    for (int u = 0; u < 4; u++) {
        int i = base + u;
        if (i < NNODES) s += g_deg[i];
    }
    #pragma unroll
    for (int off = 16; off > 0; off >>= 1)
        s += __shfl_down_sync(0xffffffff, s, off);
    if (lane == 0) ws[wid] = s;
    __syncthreads();
    if (tid == 0) {
        int t = 0;
        #pragma unroll
        for (int w = 0; w < 8; w++) t += ws[w];
        g_bsum[b] = t;
    }
}

// per-chunk scan; each block derives its own carry; zeroes g_deg
__global__ void scanB_k() {
    __shared__ int wsum[32];
    __shared__ int carry;
    int b = blockIdx.x, tid = threadIdx.x, lane = tid & 31, wid = tid >> 5;

    if (wid == 0) {
        int v0 = (lane < b) ? g_bsum[lane] : 0;
        int v1 = (lane + 32 < b) ? g_bsum[lane + 32] : 0;
        int s = v0 + v1;
        #pragma unroll
        for (int off = 16; off > 0; off >>= 1)
            s += __shfl_down_sync(0xffffffff, s, off);
        if (lane == 0) carry = s;
    }

    int i = b * 1024 + tid;
    int v = (i < NNODES) ? g_deg[i] : 0;
    int incl = v;
    #pragma unroll
    for (int off = 1; off < 32; off <<= 1) {
        int t = __shfl_up_sync(0xffffffff, incl, off);
        if (lane >= off) incl += t;
    }
    if (lane == 31) wsum[wid] = incl;
    __syncthreads();
    if (wid == 0) {
        int s = wsum[lane];
        #pragma unroll
        for (int off = 1; off < 32; off <<= 1) {
            int t = __shfl_up_sync(0xffffffff, s, off);
            if (lane >= off) s += t;
        }
        wsum[lane] = s;
    }
    __syncthreads();
    if (i < NNODES) {
        int o = carry + (wid ? wsum[wid - 1] : 0) + incl - v;  // exclusive
        g_rowptr[i] = o;
        g_dinv[i]   = rsqrtf(1.0f + (float)v);
        g_deg[i]    = 0;
    }
    if (b == 0 && tid == 0) g_rowptr[NNODES] = NEDGES;
}

__global__ void scatter_k(const int* __restrict__ ei) {
    int t = blockIdx.x * blockDim.x + threadIdx.x;
    int e8 = t * 2;
    if (e8 + 1 < NEDGES / 4) {
        int4 s0 = ((const int4*)ei)[e8];
        int4 s1 = ((const int4*)ei)[e8 + 1];
        int4 d0 = ((const int4*)(ei + NEDGES))[e8];
        int4 d1 = ((const int4*)(ei + NEDGES))[e8 + 1];
        ushort4 r0 = ((const ushort4*)g_rank16)[e8];
        ushort4 r1 = ((const ushort4*)g_rank16)[e8 + 1];
        int p0 = g_rowptr[d0.x], p1 = g_rowptr[d0.y];
        int p2 = g_rowptr[d0.z], p3 = g_rowptr[d0.w];
        int p4 = g_rowptr[d1.x], p5 = g_rowptr[d1.y];
        int p6 = g_rowptr[d1.z], p7 = g_rowptr[d1.w];
        g_col[p0 + r0.x] = s0.x;
        g_col[p1 + r0.y] = s0.y;
        g_col[p2 + r0.z] = s0.z;
        g_col[p3 + r0.w] = s0.w;
        g_col[p4 + r1.x] = s1.x;
        g_col[p5 + r1.y] = s1.y;
        g_col[p6 + r1.z] = s1.z;
        g_col[p7 + r1.w] = s1.w;
    }
}

// ---------------- bf16 / fp16 helpers ----------------
__device__ __forceinline__ void split2b(float v0, float v1, unsigned& hi, unsigned& lo) {
    __nv_bfloat16 h0 = __float2bfloat16_rn(v0);
    __nv_bfloat16 h1 = __float2bfloat16_rn(v1);
    float l0 = v0 - __bfloat162float(h0);
    float l1 = v1 - __bfloat162float(h1);
    __nv_bfloat162 hp; hp.x = h0; hp.y = h1;
    hi = *(unsigned*)&hp;
    __nv_bfloat162 lp = __floats2bfloat162_rn(l0, l1);
    lo = *(unsigned*)&lp;
}

__device__ __forceinline__ void mma_bf16(
    float& c0, float& c1, float& c2, float& c3,
    unsigned a0, unsigned a1, unsigned a2, unsigned a3,
    unsigned b0, unsigned b1)
{
    asm volatile(
        "mma.sync.aligned.m16n8k16.row.col.f32.bf16.bf16.f32 "
        "{%0,%1,%2,%3}, {%4,%5,%6,%7}, {%8,%9}, {%0,%1,%2,%3};"
        : "+f"(c0), "+f"(c1), "+f"(c2), "+f"(c3)
        : "r"(a0), "r"(a1), "r"(a2), "r"(a3), "r"(b0), "r"(b1));
}

__device__ __forceinline__ void split2h(float v0, float v1, unsigned& hi, unsigned& lo) {
    __half h0 = __float2half_rn(v0);
    __half h1 = __float2half_rn(v1);
    float l0 = v0 - __half2float(h0);
    float l1 = v1 - __half2float(h1);
    __half2 hp; hp.x = h0; hp.y = h1;
    hi = *(unsigned*)&hp;
    __half2 lp = __floats2half2_rn(l0, l1);
    lo = *(unsigned*)&lp;
}

__device__ __forceinline__ void mma_f16(
    float& c0, float& c1, float& c2, float& c3,
    unsigned a0, unsigned a1, unsigned a2, unsigned a3,
    unsigned b0, unsigned b1)
{
    asm volatile(
        "mma.sync.aligned.m16n8k16.row.col.f32.f16.f16.f32 "
        "{%0,%1,%2,%3}, {%4,%5,%6,%7}, {%8,%9}, {%0,%1,%2,%3};"
        : "+f"(c0), "+f"(c1), "+f"(c2), "+f"(c3)
        : "r"(a0), "r"(a1), "r"(a2), "r"(a3), "r"(b0), "r"(b1));
}

// ------------- layer-1 GEMM: g_bufH = (x @ W1), bf16 3-term, fp16 out --------
__global__ __launch_bounds__(256) void gemm1_k(
    const float* __restrict__ A, const float* __restrict__ W)
{
    const int FOUT = 128, MW = 4, NW = 2;
    const int BM = 128, BK = 16, K2 = BK / 2;
    const int MT = BM / (16 * MW);
    const int NT = FOUT / (8 * NW);
    const int APAD = BM + 8;
    const int WPAD = FOUT + 8;

    __shared__ unsigned Ap_hi[K2][APAD], Ap_lo[K2][APAD];
    __shared__ unsigned Wp_hi[K2][WPAD], Wp_lo[K2][WPAD];

    int tid  = threadIdx.x;
    int lane = tid & 31;
    int wid  = tid >> 5;
    int warp_m = wid % MW;
    int warp_n = wid / MW;
    int rb = blockIdx.x * BM;

    float c[MT][NT][4];
    #pragma unroll
    for (int mt = 0; mt < MT; mt++)
        #pragma unroll
        for (int nt = 0; nt < NT; nt++)
            #pragma unroll
            for (int q = 0; q < 4; q++) c[mt][nt][q] = 0.0f;

    for (int kt = 0; kt < FIN; kt += BK) {
        #pragma unroll
        for (int t = 0; t < 2; t++) {
            int idx = tid + t * 256;
            int r = idx >> 2, q = idx & 3;
            int row = rb + r;
            float4 v = make_float4(0.f, 0.f, 0.f, 0.f);
            if (row < NNODES)
                v = *(const float4*)&A[(size_t)row * FIN + kt + q * 4];
            unsigned h, l;
            split2b(v.x, v.y, h, l); Ap_hi[q * 2][r] = h;     Ap_lo[q * 2][r] = l;
            split2b(v.z, v.w, h, l); Ap_hi[q * 2 + 1][r] = h; Ap_lo[q * 2 + 1][r] = l;
        }
        {
            int k2 = tid >> 5, q = tid & 31;
            float4 v0 = *(const float4*)&W[(size_t)(kt + 2 * k2) * FOUT + q * 4];
            float4 v1 = *(const float4*)&W[(size_t)(kt + 2 * k2 + 1) * FOUT + q * 4];
            unsigned h, l;
            split2b(v0.x, v1.x, h, l); Wp_hi[k2][q * 4 + 0] = h; Wp_lo[k2][q * 4 + 0] = l;
            split2b(v0.y, v1.y, h, l); Wp_hi[k2][q * 4 + 1] = h; Wp_lo[k2][q * 4 + 1] = l;
            split2b(v0.z, v1.z, h, l); Wp_hi[k2][q * 4 + 2] = h; Wp_lo[k2][q * 4 + 2] = l;
            split2b(v0.w, v1.w, h, l); Wp_hi[k2][q * 4 + 3] = h; Wp_lo[k2][q * 4 + 3] = l;
        }
        __syncthreads();

        int t4 = lane & 3;
        int g  = lane >> 2;
        unsigned ahi[MT][4], alo[MT][4];
        #pragma unroll
        for (int mt = 0; mt < MT; mt++) {
            int m = warp_m * (MT * 16) + mt * 16 + g;
            ahi[mt][0] = Ap_hi[t4][m];         alo[mt][0] = Ap_lo[t4][m];
            ahi[mt][1] = Ap_hi[t4][m + 8];     alo[mt][1] = Ap_lo[t4][m + 8];
            ahi[mt][2] = Ap_hi[t4 + 4][m];     alo[mt][2] = Ap_lo[t4 + 4][m];
            ahi[mt][3] = Ap_hi[t4 + 4][m + 8]; alo[mt][3] = Ap_lo[t4 + 4][m + 8];
        }
        #pragma unroll
        for (int nt = 0; nt < NT; nt++) {
            int n = warp_n * (NT * 8) + nt * 8 + g;
            unsigned bh0 = Wp_hi[t4][n], bh1 = Wp_hi[t4 + 4][n];
            unsigned bl0 = Wp_lo[t4][n], bl1 = Wp_lo[t4 + 4][n];
            #pragma unroll
            for (int mt = 0; mt < MT; mt++) {
                mma_bf16(c[mt][nt][0], c[mt][nt][1], c[mt][nt][2], c[mt][nt][3],
                         ahi[mt][0], ahi[mt][1], ahi[mt][2], ahi[mt][3], bh0, bh1);
                mma_bf16(c[mt][nt][0], c[mt][nt][1], c[mt][nt][2], c[mt][nt][3],
                         ahi[mt][0], ahi[mt][1], ahi[mt][2], ahi[mt][3], bl0, bl1);
                mma_bf16(c[mt][nt][0], c[mt][nt][1], c[mt][nt][2], c[mt][nt][3],
                         alo[mt][0], alo[mt][1], alo[mt][2], alo[mt][3], bh0, bh1);
            }
        }
        __syncthreads();
    }

    #pragma unroll
    for (int mt = 0; mt < MT; mt++) {
        int r0 = rb + warp_m * (MT * 16) + mt * 16 + (lane >> 2);
        int colb = warp_n * (NT * 8) + (lane & 3) * 2;
        #pragma unroll
        for (int half = 0; half < 2; half++) {
            int row = half ? (r0 + 8) : r0;
            int q0 = half * 2;
            if (row < NNODES) {
                #pragma unroll
                for (int nt = 0; nt < NT; nt++)
                    *(__half2*)&g_bufH[(size_t)row * FOUT + colb + nt * 8] =
                        __floats2half2_rn(c[mt][nt][q0], c[mt][nt][q0 + 1]);
            }
        }
    }
}

// ------- layer-2/3 GEMM: g_bufH = (g_bufG @ W) * dinv, fp16 A, 2-term W ------
template <int FOUT, int MW, int NW>
__global__ __launch_bounds__(256) void gemm_h_k(const float* __restrict__ W)
{
    const int BM = 128, BK = 16, K2 = BK / 2;
    const int MT = BM / (16 * MW);
    const int NT = FOUT / (8 * NW);
    const int APAD = BM + 8;
    const int WPAD = FOUT + 8;

    __shared__ unsigned Ap[K2][APAD];
    __shared__ unsigned Wp_hi[K2][WPAD], Wp_lo[K2][WPAD];

    int tid  = threadIdx.x;
    int lane = tid & 31;
    int wid  = tid >> 5;
    int warp_m = wid % MW;
    int warp_n = wid / MW;
    int rb = blockIdx.x * BM;

    float c[MT][NT][4];
    #pragma unroll
    for (int mt = 0; mt < MT; mt++)
        #pragma unroll
        for (int nt = 0; nt < NT; nt++)
            #pragma unroll
            for (int q = 0; q < 4; q++) c[mt][nt][q] = 0.0f;

    for (int kt = 0; kt < FIN; kt += BK) {
        {
            int r = tid & 127, q = tid >> 7;
            int row = rb + r;
            uint4 v = make_uint4(0, 0, 0, 0);
            if (row < NNODES)
                v = *(const uint4*)&g_bufG[(size_t)row * FIN + kt + q * 8];
            Ap[q * 4 + 0][r] = v.x;
            Ap[q * 4 + 1][r] = v.y;
            Ap[q * 4 + 2][r] = v.z;
            Ap[q * 4 + 3][r] = v.w;
        }
        {
            int tasks = K2 * (FOUT / 4);
            if (tid < tasks) {
                int k2 = tid / (FOUT / 4), q = tid % (FOUT / 4);
                float4 v0 = *(const float4*)&W[(size_t)(kt + 2 * k2) * FOUT + q * 4];
                float4 v1 = *(const float4*)&W[(size_t)(kt + 2 * k2 + 1) * FOUT + q * 4];
                unsigned h, l;
                split2h(v0.x, v1.x, h, l); Wp_hi[k2][q * 4 + 0] = h; Wp_lo[k2][q * 4 + 0] = l;
                split2h(v0.y, v1.y, h, l); Wp_hi[k2][q * 4 + 1] = h; Wp_lo[k2][q * 4 + 1] = l;
                split2h(v0.z, v1.z, h, l); Wp_hi[k2][q * 4 + 2] = h; Wp_lo[k2][q * 4 + 2] = l;
                split2h(v0.w, v1.w, h, l); Wp_hi[k2][q * 4 + 3] = h; Wp_lo[k2][q * 4 + 3] = l;
            }
        }
        __syncthreads();

        int t4 = lane & 3;
        int g  = lane >> 2;
        unsigned a[MT][4];
        #pragma unroll
        for (int mt = 0; mt < MT; mt++) {
            int m = warp_m * (MT * 16) + mt * 16 + g;
            a[mt][0] = Ap[t4][m];
            a[mt][1] = Ap[t4][m + 8];
            a[mt][2] = Ap[t4 + 4][m];
            a[mt][3] = Ap[t4 + 4][m + 8];
        }
        #pragma unroll
        for (int nt = 0; nt < NT; nt++) {
            int n = warp_n * (NT * 8) + nt * 8 + g;
            unsigned bh0 = Wp_hi[t4][n], bh1 = Wp_hi[t4 + 4][n];
            unsigned bl0 = Wp_lo[t4][n], bl1 = Wp_lo[t4 + 4][n];
            #pragma unroll
            for (int mt = 0; mt < MT; mt++) {
                mma_f16(c[mt][nt][0], c[mt][nt][1], c[mt][nt][2], c[mt][nt][3],
                        a[mt][0], a[mt][1], a[mt][2], a[mt][3], bh0, bh1);
                mma_f16(c[mt][nt][0], c[mt][nt][1], c[mt][nt][2], c[mt][nt][3],
                        a[mt][0], a[mt][1], a[mt][2], a[mt][3], bl0, bl1);
            }
        }
        __syncthreads();
    }

    #pragma unroll
    for (int mt = 0; mt < MT; mt++) {
        int r0 = rb + warp_m * (MT * 16) + mt * 16 + (lane >> 2);
        int colb = warp_n * (NT * 8) + (lane & 3) * 2;
        #pragma unroll
        for (int half = 0; half < 2; half++) {
            int row = half ? (r0 + 8) : r0;
            int q0 = half * 2;
            if (row < NNODES) {
                float d = g_dinv[row];
                #pragma unroll
                for (int nt = 0; nt < NT; nt++)
                    *(__half2*)&g_bufH[(size_t)row * FOUT + colb + nt * 8] =
                        __floats2half2_rn(c[mt][nt][q0] * d, c[mt][nt][q0 + 1] * d);
            }
        }
    }
}

// ---------------- aggregate fp16 hs (half-warp per dst, uint4/lane, F=128) ----
// Main loop: exact 8-batches; tail drained with exact 4/2/1 batches (no extra loads).
template <bool SRCSCALE>
__global__ __launch_bounds__(256) void agg128h_k(
    const float* __restrict__ bias,
    const float* __restrict__ gam, const float* __restrict__ bet,
    const float* __restrict__ mu,  const float* __restrict__ var)
{
    int dst  = blockIdx.x * 16 + (threadIdx.x >> 4);
    int lane = threadIdx.x & 15;
    if (dst >= NNODES) return;

    const uint4* hs = (const uint4*)g_bufH;   // row = 16 uint4 (8 fp16 each)

    int beg = g_rowptr[dst];
    int end = g_rowptr[dst + 1];
    float d = g_dinv[dst];

    float acc[8];
    {
        uint4 v = hs[(size_t)dst * 16 + lane];
        float2 f0 = __half22float2(*(__half2*)&v.x);
        float2 f1 = __half22float2(*(__half2*)&v.y);
        float2 f2 = __half22float2(*(__half2*)&v.z);
        float2 f3 = __half22float2(*(__half2*)&v.w);
        float sd = SRCSCALE ? d : 1.0f;
        acc[0] = f0.x * sd; acc[1] = f0.y * sd;
        acc[2] = f1.x * sd; acc[3] = f1.y * sd;
        acc[4] = f2.x * sd; acc[5] = f2.y * sd;
        acc[6] = f3.x * sd; acc[7] = f3.y * sd;
    }

    int e = beg;
    for (; e + 8 <= end; e += 8) {
        uint4 v[8]; float sc[8];
        #pragma unroll
        for (int u = 0; u < 8; u++) {
            int c = g_col[e + u];
            v[u] = hs[(size_t)c * 16 + lane];
            sc[u] = SRCSCALE ? g_dinv[c] : 1.0f;
        }
        #pragma unroll
        for (int u = 0; u < 8; u++) {
            float2 f0 = __half22float2(*(__half2*)&v[u].x);
            float2 f1 = __half22float2(*(__half2*)&v[u].y);
            float2 f2 = __half22float2(*(__half2*)&v[u].z);
            float2 f3 = __half22float2(*(__half2*)&v[u].w);
            acc[0] = fmaf(f0.x, sc[u], acc[0]); acc[1] = fmaf(f0.y, sc[u], acc[1]);
            acc[2] = fmaf(f1.x, sc[u], acc[2]); acc[3] = fmaf(f1.y, sc[u], acc[3]);
            acc[4] = fmaf(f2.x, sc[u], acc[4]); acc[5] = fmaf(f2.y, sc[u], acc[5]);
            acc[6] = fmaf(f3.x, sc[u], acc[6]); acc[7] = fmaf(f3.y, sc[u], acc[7]);
        }
    }
    if (e + 4 <= end) {
        uint4 v[4]; float sc[4];
        #pragma unroll
        for (int u = 0; u < 4; u++) {
            int c = g_col[e + u];
            v[u] = hs[(size_t)c * 16 + lane];
            sc[u] = SRCSCALE ? g_dinv[c] : 1.0f;
        }
        #pragma unroll
        for (int u = 0; u < 4; u++) {
            float2 f0 = __half22float2(*(__half2*)&v[u].x);
            float2 f1 = __half22float2(*(__half2*)&v[u].y);
            float2 f2 = __half22float2(*(__half2*)&v[u].z);
            float2 f3 = __half22float2(*(__half2*)&v[u].w);
            acc[0] = fmaf(f0.x, sc[u], acc[0]); acc[1] = fmaf(f0.y, sc[u], acc[1]);
            acc[2] = fmaf(f1.x, sc[u], acc[2]); acc[3] = fmaf(f1.y, sc[u], acc[3]);
            acc[4] = fmaf(f2.x, sc[u], acc[4]); acc[5] = fmaf(f2.y, sc[u], acc[5]);
            acc[6] = fmaf(f3.x, sc[u], acc[6]); acc[7] = fmaf(f3.y, sc[u], acc[7]);
        }
        e += 4;
    }
    if (e + 2 <= end) {
        uint4 v[2]; float sc[2];
        #pragma unroll
        for (int u = 0; u < 2; u++) {
            int c = g_col[e + u];
            v[u] = hs[(size_t)c * 16 + lane];
            sc[u] = SRCSCALE ? g_dinv[c] : 1.0f;
        }
        #pragma unroll
        for (int u = 0; u < 2; u++) {
            float2 f0 = __half22float2(*(__half2*)&v[u].x);
            float2 f1 = __half22float2(*(__half2*)&v[u].y);
            float2 f2 = __half22float2(*(__half2*)&v[u].z);
            float2 f3 = __half22float2(*(__half2*)&v[u].w);
            acc[0] = fmaf(f0.x, sc[u], acc[0]); acc[1] = fmaf(f0.y, sc[u], acc[1]);
            acc[2] = fmaf(f1.x, sc[u], acc[2]); acc[3] = fmaf(f1.y, sc[u], acc[3]);
            acc[4] = fmaf(f2.x, sc[u], acc[4]); acc[5] = fmaf(f2.y, sc[u], acc[5]);
            acc[6] = fmaf(f3.x, sc[u], acc[6]); acc[7] = fmaf(f3.y, sc[u], acc[7]);
        }
        e += 2;
    }
    if (e < end) {
        int c = g_col[e];
        uint4 v = hs[(size_t)c * 16 + lane];
        float sc = SRCSCALE ? g_dinv[c] : 1.0f;
        float2 f0 = __half22float2(*(__half2*)&v.x);
        float2 f1 = __half22float2(*(__half2*)&v.y);
        float2 f2 = __half22float2(*(__half2*)&v.z);
        float2 f3 = __half22float2(*(__half2*)&v.w);
        acc[0] = fmaf(f0.x, sc, acc[0]); acc[1] = fmaf(f0.y, sc, acc[1]);
        acc[2] = fmaf(f1.x, sc, acc[2]); acc[3] = fmaf(f1.y, sc, acc[3]);
        acc[4] = fmaf(f2.x, sc, acc[4]); acc[5] = fmaf(f2.y, sc, acc[5]);
        acc[6] = fmaf(f3.x, sc, acc[6]); acc[7] = fmaf(f3.y, sc, acc[7]);
    }

    float4 b0 = ((const float4*)bias)[lane * 2], b1 = ((const float4*)bias)[lane * 2 + 1];
    float4 g0 = ((const float4*)gam)[lane * 2],  g1 = ((const float4*)gam)[lane * 2 + 1];
    float4 t0 = ((const float4*)bet)[lane * 2],  t1 = ((const float4*)bet)[lane * 2 + 1];
    float4 m0 = ((const float4*)mu)[lane * 2],   m1 = ((const float4*)mu)[lane * 2 + 1];
    float4 v0 = ((const float4*)var)[lane * 2],  v1 = ((const float4*)var)[lane * 2 + 1];
    float bb[8] = {b0.x, b0.y, b0.z, b0.w, b1.x, b1.y, b1.z, b1.w};
    float gg[8] = {g0.x, g0.y, g0.z, g0.w, g1.x, g1.y, g1.z, g1.w};
    float tt[8] = {t0.x, t0.y, t0.z, t0.w, t1.x, t1.y, t1.z, t1.w};
    float mm[8] = {m0.x, m0.y, m0.z, m0.w, m1.x, m1.y, m1.z, m1.w};
    float vv[8] = {v0.x, v0.y, v0.z, v0.w, v1.x, v1.y, v1.z, v1.w};

    float r[8];
    #pragma unroll
    for (int q = 0; q < 8; q++) {
        float val = acc[q] * d + bb[q];
        val = (val - mm[q]) * rsqrtf(vv[q] + BN_EPS) * gg[q] + tt[q];
        r[q] = val > 0.f ? val : 0.1f * val;
    }
    uint4 o;
    *(__half2*)&o.x = __floats2half2_rn(r[0], r[1]);
    *(__half2*)&o.y = __floats2half2_rn(r[2], r[3]);
    *(__half2*)&o.z = __floats2half2_rn(r[4], r[5]);
    *(__half2*)&o.w = __floats2half2_rn(r[6], r[7]);
    ((uint4*)g_bufG)[(size_t)dst * 16 + lane] = o;
}

// ---------------- aggregate F=64 fp16 hs (half-warp per dst, uint2/lane) ------
__global__ __launch_bounds__(256) void agg64h_k(
    float* __restrict__ Oext, const float* __restrict__ bias)
{
    int dst  = blockIdx.x * 16 + (threadIdx.x >> 4);
    int lane = threadIdx.x & 15;
    if (dst >= NNODES) return;

    const uint2* hs = (const uint2*)g_bufH;   // row = 16 uint2 (4 fp16 each)

    int beg = g_rowptr[dst];
    int end = g_rowptr[dst + 1];

    float acc[4];
    {
        uint2 v = hs[(size_t)dst * 16 + lane];
        float2 f0 = __half22float2(*(__half2*)&v.x);
        float2 f1 = __half22float2(*(__half2*)&v.y);
        acc[0] = f0.x; acc[1] = f0.y; acc[2] = f1.x; acc[3] = f1.y;
    }

    int e = beg;
    for (; e + 8 <= end; e += 8) {
        uint2 v[8];
        #pragma unroll
        for (int u = 0; u < 8; u++)
            v[u] = hs[(size_t)g_col[e + u] * 16 + lane];
        #pragma unroll
        for (int u = 0; u < 8; u++) {
            float2 f0 = __half22float2(*(__half2*)&v[u].x);
            float2 f1 = __half22float2(*(__half2*)&v[u].y);
            acc[0] += f0.x; acc[1] += f0.y; acc[2] += f1.x; acc[3] += f1.y;
        }
    }
    if (e + 4 <= end) {
        uint2 v[4];
        #pragma unroll
        for (int u = 0; u < 4; u++)
            v[u] = hs[(size_t)g_col[e + u] * 16 + lane];
        #pragma unroll
        for (int u = 0; u < 4; u++) {
            float2 f0 = __half22float2(*(__half2*)&v[u].x);
            float2 f1 = __half22float2(*(__half2*)&v[u].y);
            acc[0] += f0.x; acc[1] += f0.y; acc[2] += f1.x; acc[3] += f1.y;
        }
        e += 4;
    }
    if (e + 2 <= end) {
        uint2 v[2];
        #pragma unroll
        for (int u = 0; u < 2; u++)
            v[u] = hs[(size_t)g_col[e + u] * 16 + lane];
        #pragma unroll
        for (int u = 0; u < 2; u++) {
            float2 f0 = __half22float2(*(__half2*)&v[u].x);
            float2 f1 = __half22float2(*(__half2*)&v[u].y);
            acc[0] += f0.x; acc[1] += f0.y; acc[2] += f1.x; acc[3] += f1.y;
        }
        e += 2;
    }
    if (e < end) {
        uint2 v = hs[(size_t)g_col[e] * 16 + lane];
        float2 f0 = __half22float2(*(__half2*)&v.x);
        float2 f1 = __half22float2(*(__half2*)&v.y);
        acc[0] += f0.x; acc[1] += f0.y; acc[2] += f1.x; acc[3] += f1.y;
    }

    float d = g_dinv[dst];
    float4 b4 = ((const float4*)bias)[lane];
    float4 r;
    r.x = acc[0] * d + b4.x;
    r.y = acc[1] * d + b4.y;
    r.z = acc[2] * d + b4.z;
    r.w = acc[3] * d + b4.w;
    ((float4*)Oext)[(size_t)dst * 16 + lane] = r;
}

// ---------------- launch ----------------
extern "C" void kernel_launch(void* const* d_in, const int* in_sizes, int n_in,
                              void* d_out, int out_size)
{
    const float* x   = (const float*)d_in[0];
    const int*   ei  = (const int*)d_in[1];
    const float* W1 = (const float*)d_in[2];
    const float* b1 = (const float*)d_in[3];
    const float* g1 = (const float*)d_in[4];
    const float* be1= (const float*)d_in[5];
    const float* m1 = (const float*)d_in[6];
    const float* v1 = (const float*)d_in[7];
    const float* W2 = (const float*)d_in[8];
    const float* b2 = (const float*)d_in[9];
    const float* g2 = (const float*)d_in[10];
    const float* be2= (const float*)d_in[11];
    const float* m2 = (const float*)d_in[12];
    const float* v2 = (const float*)d_in[13];
    const float* W3 = (const float*)d_in[14];
    const float* b3 = (const float*)d_in[15];
    float* out = (float*)d_out;

    // side stream + events, created once on the (non-captured) correctness call
    static cudaStream_t s2 = nullptr;
    static cudaEvent_t evF = nullptr, evJ = nullptr;
    if (s2 == nullptr) {
        cudaStreamCreateWithFlags(&s2, cudaStreamNonBlocking);
        cudaEventCreateWithFlags(&evF, cudaEventDisableTiming);
        cudaEventCreateWithFlags(&evJ, cudaEventDisableTiming);
    }

    const int gblk = (NNODES + 127) / 128;
    const int ablk = (NNODES + 15) / 16;

    // fork: CSR build on s2, concurrent with GEMM1 (g_deg is 0 at entry)
    cudaEventRecord(evF, 0);
    cudaStreamWaitEvent(s2, evF, 0);
    hist_rank_k<<<(NEDGES / 8 + 255) / 256, 256, 0, s2>>>(ei);
    scan1_k<<<NCHUNK, 256, 0, s2>>>();
    scanB_k<<<NCHUNK, 1024, 0, s2>>>();
    scatter_k<<<(NEDGES / 8 + 255) / 256, 256, 0, s2>>>(ei);

    // layer 1 GEMM: x @ W1 -> g_bufH fp16 (unscaled)
    gemm1_k<<<gblk, 256>>>(x, W1);

    // join
    cudaEventRecord(evJ, s2);
    cudaStreamWaitEvent(0, evJ, 0);

    // layer 1 agg (applies dinv[src] inline), BN1 + leaky -> g_bufG fp16
    agg128h_k<true><<<ablk, 256>>>(b1, g1, be1, m1, v1);

    // layer 2: fp16 GEMM (g_bufG @ W2)*dinv -> g_bufH ; agg -> g_bufG
    gemm_h_k<128, 4, 2><<<gblk, 256>>>(W2);
    agg128h_k<false><<<ablk, 256>>>(b2, g2, be2, m2, v2);

    // layer 3: fp16 GEMM (g_bufG @ W3)*dinv -> g_bufH ; agg -> out fp32
    gemm_h_k<64, 8, 1><<<gblk, 256>>>(W3);
    agg64h_k<<<ablk, 256>>>(out, b3);
}